// round 8
// baseline (speedup 1.0000x reference)
#include <cuda_runtime.h>
#include <cuda_bf16.h>
#include <cuda_fp8.h>
#include <stdint.h>

// -------------------- problem constants --------------------
#define B_Q   4096
#define P_POS 4
#define DIM   768
#define N_KEY 20480               // B_Q + B_Q*P_POS

#define BM    128
#define BN    128
#define BKB   128                 // bytes per row per k-tile (=128 fp8 elems)
#define KTILES (DIM / BKB)        // 6
#define STAGES 3
#define NT_M  (B_Q / BM)          // 32
#define NT_N  (N_KEY / BN)        // 160
#define NQT   32                  // column tiles that are query keys
#define PW    192                 // 160 direct + 32 mirror slots

// TEMPERATURE = 0.07.  Keys scaled by 16 -> dot scaled by 256.
#define INV_T         14.285714285714286f
#define LOG2E_OVER_T  20.609929155556620f
#define EXPC          (LOG2E_OVER_T / 256.0f)   // multiplier for scaled dots
#define KEY_SCALE     16.0f

// Global key layout: k-tile-major, pre-swizzled SW128:
//   off(kt,r,c16) = kt*PLANE + (r>>3)*1024 + ((r&7)*128 + c16*16) ^ ((r&7)<<4)
#define PLANE ((size_t)N_KEY * 128)

// -------------------- scratch (__device__ globals; zero-init, no allocs) -----
__device__ __align__(256) unsigned char g_keys[(size_t)KTILES * PLANE];  // e4m3
__device__ float g_part[(size_t)B_Q * PW];   // unwritten slots stay 0 forever
__device__ float g_S[B_Q];
__device__ float g_sa[B_Q * P_POS];

// -------------------- PTX helpers --------------------
__device__ __forceinline__ uint32_t smem_u32(const void* p) {
    uint32_t a;
    asm("{ .reg .u64 t; cvta.to.shared.u64 t, %1; cvt.u32.u64 %0, t; }" : "=r"(a) : "l"(p));
    return a;
}
__device__ __forceinline__ float ex2f(float y) {
    float r; asm("ex2.approx.ftz.f32 %0, %1;" : "=f"(r) : "f"(y)); return r;
}
__device__ __forceinline__ void mbar_init(uint32_t a, uint32_t cnt) {
    asm volatile("mbarrier.init.shared.b64 [%0], %1;" :: "r"(a), "r"(cnt) : "memory");
}
__device__ __forceinline__ void mbar_expect_tx(uint32_t a, uint32_t bytes) {
    asm volatile("mbarrier.arrive.expect_tx.shared.b64 _, [%0], %1;" :: "r"(a), "r"(bytes) : "memory");
}
__device__ __forceinline__ void mbar_arrive(uint32_t a) {
    asm volatile("mbarrier.arrive.shared.b64 _, [%0];" :: "r"(a) : "memory");
}
__device__ __forceinline__ void mbar_wait(uint32_t a, uint32_t ph) {
    asm volatile(
        "{\n\t.reg .pred P;\n\t"
        "LAB_%=:\n\t"
        "mbarrier.try_wait.parity.acquire.cta.shared::cta.b64 P, [%0], %1, 0x989680;\n\t"
        "@!P bra LAB_%=;\n\t}"
        :: "r"(a), "r"(ph) : "memory");
}
__device__ __forceinline__ void bulk_g2s(uint32_t dst, const void* src, uint32_t bytes,
                                         uint32_t mbar) {
    asm volatile(
        "cp.async.bulk.shared::cta.global.mbarrier::complete_tx::bytes [%0], [%1], %2, [%3];"
        :: "r"(dst), "l"(src), "r"(bytes), "r"(mbar) : "memory");
}
__device__ __forceinline__ void ldsm_x4(uint32_t* r, uint32_t addr) {
    asm volatile("ldmatrix.sync.aligned.m8n8.x4.shared.b16 {%0,%1,%2,%3}, [%4];"
                 : "=r"(r[0]), "=r"(r[1]), "=r"(r[2]), "=r"(r[3]) : "r"(addr));
}
// fp8 e4m3 MMA: m16n8k32, fp32 accum. Fragment layout = f16 m16n8k16 with
// b16 elements replaced by fp8 pairs, so ldmatrix addressing is unchanged.
__device__ __forceinline__ void mma16832(float* c, const uint32_t* a, const uint32_t* b) {
    asm volatile(
        "mma.sync.aligned.m16n8k32.row.col.f32.e4m3.e4m3.f32 "
        "{%0,%1,%2,%3}, {%4,%5,%6,%7}, {%8,%9}, {%0,%1,%2,%3};"
        : "+f"(c[0]), "+f"(c[1]), "+f"(c[2]), "+f"(c[3])
        : "r"(a[0]), "r"(a[1]), "r"(a[2]), "r"(a[3]), "r"(b[0]), "r"(b[1]));
}

// chunk ch in [0,48): 16B chunk (kt = ch>>3 in [0,6), c16 = ch&7)
__device__ __forceinline__ size_t key_off(int r, int ch) {
    int kt = ch >> 3, c16 = ch & 7, rr = r & 7;
    return (size_t)kt * PLANE + (size_t)(r >> 3) * 1024
         + (uint32_t)((rr * 128 + c16 * 16) ^ (rr << 4));
}

// -------------------- kernel 1: L2-normalize rows -> scaled e4m3 keys --------
__global__ void prep_normalize(const float* __restrict__ q,
                               const float* __restrict__ docs) {
    int w = threadIdx.x >> 5, l = threadIdx.x & 31;
    int row = blockIdx.x * 8 + w;
    const float* src = (row < B_Q) ? (q + (size_t)row * DIM)
                                   : (docs + (size_t)(row - B_Q) * DIM);
    float ss = 0.f;
    #pragma unroll
    for (int j = 0; j < DIM / 32; ++j) { float v = src[j * 32 + l]; ss = fmaf(v, v, ss); }
    #pragma unroll
    for (int o = 16; o > 0; o >>= 1) ss += __shfl_xor_sync(0xffffffffu, ss, o);
    float sc = KEY_SCALE / fmaxf(sqrtf(ss), 1e-12f);
    for (int ch = l; ch < 48; ch += 32) {
        const float* s16 = src + ch * 16;
        uint4 u;
        unsigned char* pb = (unsigned char*)&u;
        #pragma unroll
        for (int i = 0; i < 16; ++i)
            pb[i] = __nv_cvt_float_to_fp8(s16[i] * sc, __NV_SATFINITE, __NV_E4M3);
        *(uint4*)(g_keys + key_off(row, ch)) = u;
    }
}

// -------------------- kernel 2: positive dots, full fp32 from raw inputs -----
// block i: 4 warps, warp w handles positive w. Fused normalize + dot.
__global__ void pos_dots(const float* __restrict__ q,
                         const float* __restrict__ docs) {
    int i = blockIdx.x;
    int w = threadIdx.x >> 5, l = threadIdx.x & 31;
    const float* qa = q + (size_t)i * DIM;
    const float* db = docs + (size_t)(i * P_POS + w) * DIM;
    float sq = 0.f, sd = 0.f, dt = 0.f;
    #pragma unroll
    for (int j = 0; j < DIM / 32; ++j) {
        float a = qa[j * 32 + l], b = db[j * 32 + l];
        sq = fmaf(a, a, sq); sd = fmaf(b, b, sd); dt = fmaf(a, b, dt);
    }
    #pragma unroll
    for (int o = 16; o > 0; o >>= 1) {
        sq += __shfl_xor_sync(0xffffffffu, sq, o);
        sd += __shfl_xor_sync(0xffffffffu, sd, o);
        dt += __shfl_xor_sync(0xffffffffu, dt, o);
    }
    if (l == 0)
        g_sa[i * P_POS + w] = dt / fmaxf(sqrtf(sq) * sqrtf(sd), 1e-12f);
}

// -------------------- kernel 3: fp8 bulk-copy pipelined GEMM + exp/rowsum ----
#define ST_A(s) (128 + (s) * 32768)
#define ST_B(s) (128 + (s) * 32768 + 16384)
#define SM_DYN  (128 + STAGES * 32768)

__global__ __launch_bounds__(256, 2) void gemm_exp_rowsum() {
    int bn = blockIdx.x, bm = blockIdx.y;
    if (bn < NQT && bn > bm) return;           // upper-triangle q-q tile: mirrored
    bool do_mirror = (bn < NQT) && (bn < bm);
    bool dtile     = (bn < NQT) && (bn == bm); // contains global diagonal

    extern __shared__ char smem[];
    __shared__ float rsum[4][128];
    __shared__ float csum[2][128];
    uint32_t sb = smem_u32(smem);
    uint32_t mb_full  = sb;
    uint32_t mb_empty = sb + 24;

    int t = threadIdx.x, warp = t >> 5, lane = t & 31;
    int wm = warp >> 2, wn = warp & 3;          // warp tile 64(M) x 32(N)
    int gr = lane >> 2, gc = lane & 3;

    if (t == 0) {
        #pragma unroll
        for (int s = 0; s < STAGES; ++s) {
            mbar_init(mb_full + s * 8, 1);
            mbar_init(mb_empty + s * 8, 8);
        }
    }
    __syncthreads();

    const unsigned char* keys = g_keys;
    size_t aoff = (size_t)bm * 16384;
    size_t boff = (size_t)bn * 16384;

    if (t == 0) {
        #pragma unroll
        for (int k = 0; k < STAGES; ++k) {
            uint32_t f = mb_full + k * 8;
            mbar_expect_tx(f, 32768);
            bulk_g2s(sb + ST_A(k), keys + (size_t)k * PLANE + aoff, 16384, f);
            bulk_g2s(sb + ST_B(k), keys + (size_t)k * PLANE + boff, 16384, f);
        }
    }

    float c[4][4][4];
    #pragma unroll
    for (int mt = 0; mt < 4; ++mt)
        #pragma unroll
        for (int nt = 0; nt < 4; ++nt)
            #pragma unroll
            for (int r = 0; r < 4; ++r) c[mt][nt][r] = 0.f;

    int a_mr = (lane & 15);
    int a_cb = (lane >> 4) * 16;
    int b_nr = ((lane >> 3) & 1) * 8 + (lane & 7);
    int b_cb = (lane >> 4) * 16;

    for (int kt = 0; kt < KTILES; ++kt) {
        int s = kt % STAGES;
        uint32_t ph = (uint32_t)((kt / STAGES) & 1);
        mbar_wait(mb_full + s * 8, ph);

        uint32_t As = sb + ST_A(s), Bs = sb + ST_B(s);
        #pragma unroll
        for (int ks = 0; ks < 4; ++ks) {       // four k32 fp8 steps (32B each)
            uint32_t a[4][4], b[4][2];
            #pragma unroll
            for (int mt = 0; mt < 4; ++mt) {
                int mr = wm * 64 + mt * 16 + a_mr;
                uint32_t cb = (uint32_t)((ks * 32 + a_cb) ^ ((mr & 7) << 4));
                ldsm_x4(a[mt], As + mr * 128 + cb);
            }
            #pragma unroll
            for (int nt2 = 0; nt2 < 2; ++nt2) {
                int nr = wn * 32 + nt2 * 16 + b_nr;
                uint32_t cb = (uint32_t)((ks * 32 + b_cb) ^ ((nr & 7) << 4));
                uint32_t r4[4];
                ldsm_x4(r4, Bs + nr * 128 + cb);
                b[nt2 * 2 + 0][0] = r4[0]; b[nt2 * 2 + 0][1] = r4[2];
                b[nt2 * 2 + 1][0] = r4[1]; b[nt2 * 2 + 1][1] = r4[3];
            }
            #pragma unroll
            for (int mt = 0; mt < 4; ++mt)
                #pragma unroll
                for (int nt = 0; nt < 4; ++nt)
                    mma16832(c[mt][nt], a[mt], b[nt]);
        }

        __syncwarp();
        if (lane == 0) mbar_arrive(mb_empty + s * 8);
        if (t == 0 && kt + STAGES < KTILES) {
            mbar_wait(mb_empty + s * 8, ph);
            int ktn = kt + STAGES;
            uint32_t f = mb_full + s * 8;
            mbar_expect_tx(f, 32768);
            bulk_g2s(sb + ST_A(s), keys + (size_t)ktn * PLANE + aoff, 16384, f);
            bulk_g2s(sb + ST_B(s), keys + (size_t)ktn * PLANE + boff, 16384, f);
        }
    }

    // ---- epilogue: exp once; diag tiles zero the row==col element exactly ----
    float cs0[4] = {0.f, 0.f, 0.f, 0.f};
    float cs1[4] = {0.f, 0.f, 0.f, 0.f};
    #pragma unroll
    for (int mt = 0; mt < 4; ++mt) {
        float s0 = 0.f, s1 = 0.f;
        int r0 = wm * 64 + mt * 16 + gr;       // rows for c[0],c[1]; +8 for c[2],c[3]
        #pragma unroll
        for (int nt = 0; nt < 4; ++nt) {
            int n0 = wn * 32 + nt * 8 + 2 * gc;
            float e0 = ex2f(c[mt][nt][0] * EXPC);
            float e1 = ex2f(c[mt][nt][1] * EXPC);
            float e2 = ex2f(c[mt][nt][2] * EXPC);
            float e3 = ex2f(c[mt][nt][3] * EXPC);
            if (dtile) {                        // exact diagonal exclusion
                if (r0 == n0)         e0 = 0.f;
                if (r0 == n0 + 1)     e1 = 0.f;
                if (r0 + 8 == n0)     e2 = 0.f;
                if (r0 + 8 == n0 + 1) e3 = 0.f;
            }
            s0 += e0 + e1;  s1 += e2 + e3;
            cs0[nt] += e0 + e2;  cs1[nt] += e1 + e3;
        }
        s0 += __shfl_xor_sync(0xffffffffu, s0, 1);
        s0 += __shfl_xor_sync(0xffffffffu, s0, 2);
        s1 += __shfl_xor_sync(0xffffffffu, s1, 1);
        s1 += __shfl_xor_sync(0xffffffffu, s1, 2);
        if (gc == 0) {
            rsum[wn][wm * 64 + mt * 16 + gr]     = s0;
            rsum[wn][wm * 64 + mt * 16 + 8 + gr] = s1;
        }
    }
    if (do_mirror) {
        #pragma unroll
        for (int nt = 0; nt < 4; ++nt) {
            #pragma unroll
            for (int o = 4; o <= 16; o <<= 1) {
                cs0[nt] += __shfl_xor_sync(0xffffffffu, cs0[nt], o);
                cs1[nt] += __shfl_xor_sync(0xffffffffu, cs1[nt], o);
            }
        }
        if (gr == 0) {
            #pragma unroll
            for (int nt = 0; nt < 4; ++nt) {
                int n = wn * 32 + nt * 8 + 2 * gc;
                if (wm == 0) { csum[0][n] = cs0[nt]; csum[0][n + 1] = cs1[nt]; }
                else         { csum[1][n] = cs0[nt]; csum[1][n + 1] = cs1[nt]; }
            }
        }
    }
    __syncthreads();
    if (t < 128) {
        g_part[(size_t)(bm * BM + t) * PW + bn] =
            rsum[0][t] + rsum[1][t] + rsum[2][t] + rsum[3][t];
        if (do_mirror)
            g_part[(size_t)(bn * BN + t) * PW + 160 + bm] = csum[0][t] + csum[1][t];
    }
}

// -------------------- kernel 4: reduce partials -> S[row] --------------------
__global__ void reduce_S() {
    int row = blockIdx.x * 8 + (threadIdx.x >> 5);
    int l   = threadIdx.x & 31;
    float s = 0.f;
    #pragma unroll
    for (int j = 0; j < PW / 32; ++j) s += g_part[(size_t)row * PW + j * 32 + l];
    for (int o = 16; o > 0; o >>= 1) s += __shfl_xor_sync(0xffffffffu, s, o);
    if (l == 0) g_S[row] = s;
}

// -------------------- kernel 5: finalize loss --------------------------------
// S excludes the q-q diagonal already, so: denom = S - sum_n exp(sa_n) + exp(sa)
__global__ void finalize_loss(float* __restrict__ out, int out_size) {
    int t = threadIdx.x;
    float acc = 0.f;
    for (int i = t; i < B_Q; i += 512) {
        float e[4], su = 0.f, sa[4];
        #pragma unroll
        for (int n = 0; n < 4; ++n) {
            sa[n] = g_sa[i * P_POS + n];
            e[n]  = ex2f(sa[n] * LOG2E_OVER_T);
            su   += e[n];
        }
        float base = g_S[i] - su;
        #pragma unroll
        for (int n = 0; n < 4; ++n)
            acc += logf(base + e[n]) - sa[n] * INV_T;
    }
    __shared__ float red[512];
    red[t] = acc; __syncthreads();
    for (int s = 256; s > 0; s >>= 1) { if (t < s) red[t] += red[t + s]; __syncthreads(); }
    if (t == 0) {
        float loss = red[0] / (float)(B_Q * P_POS);
        for (int j = 0; j < out_size; ++j) out[j] = loss;
    }
}

// -------------------- launch --------------------------------------------------
extern "C" void kernel_launch(void* const* d_in, const int* in_sizes, int n_in,
                              void* d_out, int out_size) {
    (void)in_sizes; (void)n_in;
    const float* q    = (const float*)d_in[0];
    const float* docs = (const float*)d_in[1];
    float* out        = (float*)d_out;

    cudaFuncSetAttribute(gemm_exp_rowsum, cudaFuncAttributeMaxDynamicSharedMemorySize, SM_DYN);

    prep_normalize<<<N_KEY / 8, 256>>>(q, docs);
    pos_dots<<<B_Q, 128>>>(q, docs);
    gemm_exp_rowsum<<<dim3(NT_N, NT_M), 256, SM_DYN>>>();
    reduce_S<<<B_Q / 8, 256>>>();
    finalize_loss<<<1, 512>>>(out, out_size);
}

// round 9
// speedup vs baseline: 1.0644x; 1.0644x over previous
#include <cuda_runtime.h>
#include <cuda_bf16.h>
#include <stdint.h>

// -------------------- problem constants --------------------
#define B_Q   4096
#define P_POS 4
#define DIM   768
#define N_KEY 20480               // B_Q + B_Q*P_POS

#define BM    128
#define BN    128
#define KTILES 12                 // 64 bf16 (=128B) per k-tile
#define STAGES 3
#define NT_M  (B_Q / BM)          // 32
#define NT_N  (N_KEY / BN)        // 160
#define NQT   32                  // column tiles that are query keys
#define PW    192                 // 160 direct + 32 mirror slots

// TEMPERATURE = 0.07
#define INV_T         14.285714285714286f
#define LOG2E_OVER_T  20.609929155556620f
// keys pre-scaled by sqrt(log2e/T): dot of stored keys = cos_sim * log2e/T,
// so exp(cos/T) = ex2(dot) with no epilogue multiply.
#define KEY_PRESCALE  4.539816203f

// Global key layout: k-tile-major, pre-swizzled SW128:
//   off(kt,r,c16) = kt*PLANE + (r>>3)*1024 + ((r&7)*128 + c16*16) ^ ((r&7)<<4)
#define PLANE ((size_t)N_KEY * 128)

// -------------------- scratch (__device__ globals; zero-init, no allocs) -----
__device__ __align__(256) unsigned char g_keys[(size_t)KTILES * PLANE];  // bf16
__device__ float g_part[(size_t)B_Q * PW];   // unwritten slots stay 0 forever
__device__ float g_S[B_Q];
__device__ float g_sa[B_Q * P_POS];

// -------------------- PTX helpers --------------------
__device__ __forceinline__ uint32_t smem_u32(const void* p) {
    uint32_t a;
    asm("{ .reg .u64 t; cvta.to.shared.u64 t, %1; cvt.u32.u64 %0, t; }" : "=r"(a) : "l"(p));
    return a;
}
__device__ __forceinline__ float ex2f(float y) {
    float r; asm("ex2.approx.ftz.f32 %0, %1;" : "=f"(r) : "f"(y)); return r;
}
__device__ __forceinline__ void mbar_init(uint32_t a, uint32_t cnt) {
    asm volatile("mbarrier.init.shared.b64 [%0], %1;" :: "r"(a), "r"(cnt) : "memory");
}
__device__ __forceinline__ void mbar_expect_tx(uint32_t a, uint32_t bytes) {
    asm volatile("mbarrier.arrive.expect_tx.shared.b64 _, [%0], %1;" :: "r"(a), "r"(bytes) : "memory");
}
__device__ __forceinline__ void mbar_arrive(uint32_t a) {
    asm volatile("mbarrier.arrive.shared.b64 _, [%0];" :: "r"(a) : "memory");
}
__device__ __forceinline__ void mbar_wait(uint32_t a, uint32_t ph) {
    asm volatile(
        "{\n\t.reg .pred P;\n\t"
        "LAB_%=:\n\t"
        "mbarrier.try_wait.parity.acquire.cta.shared::cta.b64 P, [%0], %1, 0x989680;\n\t"
        "@!P bra LAB_%=;\n\t}"
        :: "r"(a), "r"(ph) : "memory");
}
__device__ __forceinline__ void bulk_g2s(uint32_t dst, const void* src, uint32_t bytes,
                                         uint32_t mbar) {
    asm volatile(
        "cp.async.bulk.shared::cta.global.mbarrier::complete_tx::bytes [%0], [%1], %2, [%3];"
        :: "r"(dst), "l"(src), "r"(bytes), "r"(mbar) : "memory");
}
__device__ __forceinline__ void ldsm_x4(uint32_t* r, uint32_t addr) {
    asm volatile("ldmatrix.sync.aligned.m8n8.x4.shared.b16 {%0,%1,%2,%3}, [%4];"
                 : "=r"(r[0]), "=r"(r[1]), "=r"(r[2]), "=r"(r[3]) : "r"(addr));
}
__device__ __forceinline__ void mma16816(float* c, const uint32_t* a, const uint32_t* b) {
    asm volatile(
        "mma.sync.aligned.m16n8k16.row.col.f32.bf16.bf16.f32 "
        "{%0,%1,%2,%3}, {%4,%5,%6,%7}, {%8,%9}, {%0,%1,%2,%3};"
        : "+f"(c[0]), "+f"(c[1]), "+f"(c[2]), "+f"(c[3])
        : "r"(a[0]), "r"(a[1]), "r"(a[2]), "r"(a[3]), "r"(b[0]), "r"(b[1]));
}

// chunk ch in [0,96): 16B chunk of a row (kt = ch>>3 in [0,12), c16 = ch&7)
__device__ __forceinline__ size_t key_off(int r, int ch) {
    int kt = ch >> 3, c16 = ch & 7, rr = r & 7;
    return (size_t)kt * PLANE + (size_t)(r >> 3) * 1024
         + (uint32_t)((rr * 128 + c16 * 16) ^ (rr << 4));
}

// -------------------- kernel 1: L2-normalize rows -> prescaled bf16 keys -----
__global__ void prep_normalize(const float* __restrict__ q,
                               const float* __restrict__ docs) {
    int w = threadIdx.x >> 5, l = threadIdx.x & 31;
    int row = blockIdx.x * 8 + w;
    const float* src = (row < B_Q) ? (q + (size_t)row * DIM)
                                   : (docs + (size_t)(row - B_Q) * DIM);
    float ss = 0.f;
    #pragma unroll
    for (int j = 0; j < DIM / 32; ++j) { float v = src[j * 32 + l]; ss = fmaf(v, v, ss); }
    #pragma unroll
    for (int o = 16; o > 0; o >>= 1) ss += __shfl_xor_sync(0xffffffffu, ss, o);
    float sc = KEY_PRESCALE / fmaxf(sqrtf(ss), 1e-12f);
    #pragma unroll
    for (int c3 = 0; c3 < 3; ++c3) {
        int ch = c3 * 32 + l;
        const float* s8 = src + ch * 8;
        uint4 u;
        uint32_t* pu = (uint32_t*)&u;
        #pragma unroll
        for (int i = 0; i < 4; ++i) {
            __nv_bfloat162 h = __floats2bfloat162_rn(s8[2 * i] * sc, s8[2 * i + 1] * sc);
            pu[i] = *(uint32_t*)&h;
        }
        *(uint4*)(g_keys + key_off(row, ch)) = u;
    }
}

// -------------------- kernel 2: positive dots, full fp32 from raw inputs -----
__global__ void pos_dots(const float* __restrict__ q,
                         const float* __restrict__ docs) {
    int i = blockIdx.x;
    int w = threadIdx.x >> 5, l = threadIdx.x & 31;
    const float* qa = q + (size_t)i * DIM;
    const float* db = docs + (size_t)(i * P_POS + w) * DIM;
    float sq = 0.f, sd = 0.f, dt = 0.f;
    #pragma unroll
    for (int j = 0; j < DIM / 32; ++j) {
        float a = qa[j * 32 + l], b = db[j * 32 + l];
        sq = fmaf(a, a, sq); sd = fmaf(b, b, sd); dt = fmaf(a, b, dt);
    }
    #pragma unroll
    for (int o = 16; o > 0; o >>= 1) {
        sq += __shfl_xor_sync(0xffffffffu, sq, o);
        sd += __shfl_xor_sync(0xffffffffu, sd, o);
        dt += __shfl_xor_sync(0xffffffffu, dt, o);
    }
    if (l == 0)
        g_sa[i * P_POS + w] = dt / fmaxf(sqrtf(sq) * sqrtf(sd), 1e-12f);
}

// -------------------- kernel 3: bulk-copy pipelined bf16 GEMM + exp/rowsum ---
#define ST_A(s) (128 + (s) * 32768)
#define ST_B(s) (128 + (s) * 32768 + 16384)
#define SM_DYN  (128 + STAGES * 32768)

__global__ __launch_bounds__(256, 2) void gemm_exp_rowsum() {
    int bn = blockIdx.x, bm = blockIdx.y;
    if (bn < NQT && bn > bm) return;           // upper-triangle q-q tile: mirrored
    bool do_mirror = (bn < NQT) && (bn < bm);
    bool dtile     = (bn == bm) && (bn < NQT); // contains global diagonal

    extern __shared__ char smem[];
    __shared__ float rsum[4][128];
    __shared__ float csum[2][128];
    uint32_t sb = smem_u32(smem);
    uint32_t mb_full  = sb;
    uint32_t mb_empty = sb + 24;

    int t = threadIdx.x, warp = t >> 5, lane = t & 31;
    int wm = warp >> 2, wn = warp & 3;          // warp tile 64(M) x 32(N)
    int gr = lane >> 2, gc = lane & 3;

    if (t == 0) {
        #pragma unroll
        for (int s = 0; s < STAGES; ++s) {
            mbar_init(mb_full + s * 8, 1);
            mbar_init(mb_empty + s * 8, 8);
        }
    }
    __syncthreads();

    const unsigned char* keys = g_keys;
    size_t aoff = (size_t)bm * 16384;
    size_t boff = (size_t)bn * 16384;

    if (t == 0) {
        #pragma unroll
        for (int k = 0; k < STAGES; ++k) {
            uint32_t f = mb_full + k * 8;
            mbar_expect_tx(f, 32768);
            bulk_g2s(sb + ST_A(k), keys + (size_t)k * PLANE + aoff, 16384, f);
            bulk_g2s(sb + ST_B(k), keys + (size_t)k * PLANE + boff, 16384, f);
        }
    }

    float c[4][4][4];
    #pragma unroll
    for (int mt = 0; mt < 4; ++mt)
        #pragma unroll
        for (int nt = 0; nt < 4; ++nt)
            #pragma unroll
            for (int r = 0; r < 4; ++r) c[mt][nt][r] = 0.f;

    int a_mr = (lane & 15);
    int a_cb = (lane >> 4) * 16;
    int b_nr = ((lane >> 3) & 1) * 8 + (lane & 7);
    int b_cb = (lane >> 4) * 16;

    #pragma unroll 3
    for (int kt = 0; kt < KTILES; ++kt) {
        int s = kt % STAGES;
        uint32_t ph = (uint32_t)((kt / STAGES) & 1);
        mbar_wait(mb_full + s * 8, ph);

        uint32_t As = sb + ST_A(s), Bs = sb + ST_B(s);
        #pragma unroll
        for (int ks = 0; ks < 4; ++ks) {
            uint32_t a[4][4], b[4][2];
            #pragma unroll
            for (int mt = 0; mt < 4; ++mt) {
                int mr = wm * 64 + mt * 16 + a_mr;
                uint32_t cb = (uint32_t)((ks * 32 + a_cb) ^ ((mr & 7) << 4));
                ldsm_x4(a[mt], As + mr * 128 + cb);
            }
            #pragma unroll
            for (int nt2 = 0; nt2 < 2; ++nt2) {
                int nr = wn * 32 + nt2 * 16 + b_nr;
                uint32_t cb = (uint32_t)((ks * 32 + b_cb) ^ ((nr & 7) << 4));
                uint32_t r4[4];
                ldsm_x4(r4, Bs + nr * 128 + cb);
                b[nt2 * 2 + 0][0] = r4[0]; b[nt2 * 2 + 0][1] = r4[2];
                b[nt2 * 2 + 1][0] = r4[1]; b[nt2 * 2 + 1][1] = r4[3];
            }
            #pragma unroll
            for (int mt = 0; mt < 4; ++mt)
                #pragma unroll
                for (int nt = 0; nt < 4; ++nt)
                    mma16816(c[mt][nt], a[mt], b[nt]);
        }

        __syncwarp();
        if (lane == 0) mbar_arrive(mb_empty + s * 8);
        if (t == 0 && kt + STAGES < KTILES) {
            mbar_wait(mb_empty + s * 8, ph);
            int ktn = kt + STAGES;
            uint32_t f = mb_full + s * 8;
            mbar_expect_tx(f, 32768);
            bulk_g2s(sb + ST_A(s), keys + (size_t)ktn * PLANE + aoff, 16384, f);
            bulk_g2s(sb + ST_B(s), keys + (size_t)ktn * PLANE + boff, 16384, f);
        }
    }

    // ---- epilogue: ex2 directly (scale folded into keys); exact diag excl ----
    float cs0[4] = {0.f, 0.f, 0.f, 0.f};
    float cs1[4] = {0.f, 0.f, 0.f, 0.f};
    #pragma unroll
    for (int mt = 0; mt < 4; ++mt) {
        float s0 = 0.f, s1 = 0.f;
        int r0 = wm * 64 + mt * 16 + gr;
        #pragma unroll
        for (int nt = 0; nt < 4; ++nt) {
            int n0 = wn * 32 + nt * 8 + 2 * gc;
            float e0 = ex2f(c[mt][nt][0]);
            float e1 = ex2f(c[mt][nt][1]);
            float e2 = ex2f(c[mt][nt][2]);
            float e3 = ex2f(c[mt][nt][3]);
            if (dtile) {                        // exact diagonal exclusion
                if (r0 == n0)         e0 = 0.f;
                if (r0 == n0 + 1)     e1 = 0.f;
                if (r0 + 8 == n0)     e2 = 0.f;
                if (r0 + 8 == n0 + 1) e3 = 0.f;
            }
            s0 += e0 + e1;  s1 += e2 + e3;
            cs0[nt] += e0 + e2;  cs1[nt] += e1 + e3;
        }
        s0 += __shfl_xor_sync(0xffffffffu, s0, 1);
        s0 += __shfl_xor_sync(0xffffffffu, s0, 2);
        s1 += __shfl_xor_sync(0xffffffffu, s1, 1);
        s1 += __shfl_xor_sync(0xffffffffu, s1, 2);
        if (gc == 0) {
            rsum[wn][wm * 64 + mt * 16 + gr]     = s0;
            rsum[wn][wm * 64 + mt * 16 + 8 + gr] = s1;
        }
    }
    if (do_mirror) {
        #pragma unroll
        for (int nt = 0; nt < 4; ++nt) {
            #pragma unroll
            for (int o = 4; o <= 16; o <<= 1) {
                cs0[nt] += __shfl_xor_sync(0xffffffffu, cs0[nt], o);
                cs1[nt] += __shfl_xor_sync(0xffffffffu, cs1[nt], o);
            }
        }
        if (gr == 0) {
            #pragma unroll
            for (int nt = 0; nt < 4; ++nt) {
                int n = wn * 32 + nt * 8 + 2 * gc;
                if (wm == 0) { csum[0][n] = cs0[nt]; csum[0][n + 1] = cs1[nt]; }
                else         { csum[1][n] = cs0[nt]; csum[1][n + 1] = cs1[nt]; }
            }
        }
    }
    __syncthreads();
    if (t < 128) {
        g_part[(size_t)(bm * BM + t) * PW + bn] =
            rsum[0][t] + rsum[1][t] + rsum[2][t] + rsum[3][t];
        if (do_mirror)
            g_part[(size_t)(bn * BN + t) * PW + 160 + bm] = csum[0][t] + csum[1][t];
    }
}

// -------------------- kernel 4: reduce partials -> S[row] --------------------
__global__ void reduce_S() {
    int row = blockIdx.x * 8 + (threadIdx.x >> 5);
    int l   = threadIdx.x & 31;
    float s = 0.f;
    #pragma unroll
    for (int j = 0; j < PW / 32; ++j) s += g_part[(size_t)row * PW + j * 32 + l];
    for (int o = 16; o > 0; o >>= 1) s += __shfl_xor_sync(0xffffffffu, s, o);
    if (l == 0) g_S[row] = s;
}

// -------------------- kernel 5: finalize loss --------------------------------
// S already excludes the q-q diagonal: denom = S - sum_n exp(sa_n) + exp(sa)
__global__ void finalize_loss(float* __restrict__ out, int out_size) {
    int t = threadIdx.x;
    float acc = 0.f;
    for (int i = t; i < B_Q; i += 512) {
        float e[4], su = 0.f, sa[4];
        #pragma unroll
        for (int n = 0; n < 4; ++n) {
            sa[n] = g_sa[i * P_POS + n];
            e[n]  = ex2f(sa[n] * LOG2E_OVER_T);
            su   += e[n];
        }
        float base = g_S[i] - su;
        #pragma unroll
        for (int n = 0; n < 4; ++n)
            acc += logf(base + e[n]) - sa[n] * INV_T;
    }
    __shared__ float red[512];
    red[t] = acc; __syncthreads();
    for (int s = 256; s > 0; s >>= 1) { if (t < s) red[t] += red[t + s]; __syncthreads(); }
    if (t == 0) {
        float loss = red[0] / (float)(B_Q * P_POS);
        for (int j = 0; j < out_size; ++j) out[j] = loss;
    }
}

// -------------------- launch --------------------------------------------------
extern "C" void kernel_launch(void* const* d_in, const int* in_sizes, int n_in,
                              void* d_out, int out_size) {
    (void)in_sizes; (void)n_in;
    const float* q    = (const float*)d_in[0];
    const float* docs = (const float*)d_in[1];
    float* out        = (float*)d_out;

    cudaFuncSetAttribute(gemm_exp_rowsum, cudaFuncAttributeMaxDynamicSharedMemorySize, SM_DYN);

    prep_normalize<<<N_KEY / 8, 256>>>(q, docs);
    pos_dots<<<B_Q, 128>>>(q, docs);
    gemm_exp_rowsum<<<dim3(NT_N, NT_M), 256, SM_DYN>>>();
    reduce_S<<<B_Q / 8, 256>>>();
    finalize_loss<<<1, 512>>>(out, out_size);
}

// round 10
// speedup vs baseline: 1.0900x; 1.0240x over previous
#include <cuda_runtime.h>
#include <cuda_bf16.h>
#include <stdint.h>

// -------------------- problem constants --------------------
#define B_Q   4096
#define P_POS 4
#define DIM   768
#define N_KEY 20480               // B_Q + B_Q*P_POS

#define BM    128
#define BN    128
#define KTILES 12                 // 64 bf16 (=128B) per k-tile
#define STAGES 3
#define NT_M  (B_Q / BM)          // 32
#define NT_N  (N_KEY / BN)        // 160
#define NQT   32                  // column tiles that are query keys
#define PW    192                 // 160 direct + 32 mirror slots

// TEMPERATURE = 0.07
#define INV_T         14.285714285714286f
#define LOG2E_OVER_T  20.609929155556620f
// keys pre-scaled by sqrt(log2e/T): dot of stored keys = cos_sim * log2e/T,
// so exp(cos/T) = ex2(dot) with no epilogue multiply.
#define KEY_PRESCALE  4.539816203f

// Global key layout: k-tile-major, pre-swizzled SW128:
//   off(kt,r,c16) = kt*PLANE + (r>>3)*1024 + ((r&7)*128 + c16*16) ^ ((r&7)<<4)
#define PLANE ((size_t)N_KEY * 128)

// -------------------- scratch (__device__ globals; zero-init, no allocs) -----
__device__ __align__(256) unsigned char g_keys[(size_t)KTILES * PLANE];  // bf16
__device__ float g_part[(size_t)B_Q * PW];   // unwritten slots stay 0 forever
__device__ float g_rowloss[B_Q];
__device__ float g_sa[B_Q * P_POS];

// -------------------- PTX helpers --------------------
__device__ __forceinline__ uint32_t smem_u32(const void* p) {
    uint32_t a;
    asm("{ .reg .u64 t; cvta.to.shared.u64 t, %1; cvt.u32.u64 %0, t; }" : "=r"(a) : "l"(p));
    return a;
}
__device__ __forceinline__ float ex2f(float y) {
    float r; asm("ex2.approx.ftz.f32 %0, %1;" : "=f"(r) : "f"(y)); return r;
}
__device__ __forceinline__ void mbar_init(uint32_t a, uint32_t cnt) {
    asm volatile("mbarrier.init.shared.b64 [%0], %1;" :: "r"(a), "r"(cnt) : "memory");
}
__device__ __forceinline__ void mbar_expect_tx(uint32_t a, uint32_t bytes) {
    asm volatile("mbarrier.arrive.expect_tx.shared.b64 _, [%0], %1;" :: "r"(a), "r"(bytes) : "memory");
}
__device__ __forceinline__ void mbar_arrive(uint32_t a) {
    asm volatile("mbarrier.arrive.shared.b64 _, [%0];" :: "r"(a) : "memory");
}
__device__ __forceinline__ void mbar_wait(uint32_t a, uint32_t ph) {
    asm volatile(
        "{\n\t.reg .pred P;\n\t"
        "LAB_%=:\n\t"
        "mbarrier.try_wait.parity.acquire.cta.shared::cta.b64 P, [%0], %1, 0x989680;\n\t"
        "@!P bra LAB_%=;\n\t}"
        :: "r"(a), "r"(ph) : "memory");
}
__device__ __forceinline__ void bulk_g2s(uint32_t dst, const void* src, uint32_t bytes,
                                         uint32_t mbar) {
    asm volatile(
        "cp.async.bulk.shared::cta.global.mbarrier::complete_tx::bytes [%0], [%1], %2, [%3];"
        :: "r"(dst), "l"(src), "r"(bytes), "r"(mbar) : "memory");
}
__device__ __forceinline__ void ldsm_x4(uint32_t* r, uint32_t addr) {
    asm volatile("ldmatrix.sync.aligned.m8n8.x4.shared.b16 {%0,%1,%2,%3}, [%4];"
                 : "=r"(r[0]), "=r"(r[1]), "=r"(r[2]), "=r"(r[3]) : "r"(addr));
}
__device__ __forceinline__ void mma16816(float* c, const uint32_t* a, const uint32_t* b) {
    asm volatile(
        "mma.sync.aligned.m16n8k16.row.col.f32.bf16.bf16.f32 "
        "{%0,%1,%2,%3}, {%4,%5,%6,%7}, {%8,%9}, {%0,%1,%2,%3};"
        : "+f"(c[0]), "+f"(c[1]), "+f"(c[2]), "+f"(c[3])
        : "r"(a[0]), "r"(a[1]), "r"(a[2]), "r"(a[3]), "r"(b[0]), "r"(b[1]));
}

// chunk ch in [0,96): 16B chunk of a row (kt = ch>>3 in [0,12), c16 = ch&7)
__device__ __forceinline__ size_t key_off(int r, int ch) {
    int kt = ch >> 3, c16 = ch & 7, rr = r & 7;
    return (size_t)kt * PLANE + (size_t)(r >> 3) * 1024
         + (uint32_t)((rr * 128 + c16 * 16) ^ (rr << 4));
}

// -------------------- kernel 1: L2-normalize rows -> prescaled bf16 keys -----
__global__ void prep_normalize(const float* __restrict__ q,
                               const float* __restrict__ docs) {
    int w = threadIdx.x >> 5, l = threadIdx.x & 31;
    int row = blockIdx.x * 8 + w;
    const float* src = (row < B_Q) ? (q + (size_t)row * DIM)
                                   : (docs + (size_t)(row - B_Q) * DIM);
    float ss = 0.f;
    #pragma unroll
    for (int j = 0; j < DIM / 32; ++j) { float v = src[j * 32 + l]; ss = fmaf(v, v, ss); }
    #pragma unroll
    for (int o = 16; o > 0; o >>= 1) ss += __shfl_xor_sync(0xffffffffu, ss, o);
    float sc = KEY_PRESCALE / fmaxf(sqrtf(ss), 1e-12f);
    #pragma unroll
    for (int c3 = 0; c3 < 3; ++c3) {
        int ch = c3 * 32 + l;
        const float* s8 = src + ch * 8;
        uint4 u;
        uint32_t* pu = (uint32_t*)&u;
        #pragma unroll
        for (int i = 0; i < 4; ++i) {
            __nv_bfloat162 h = __floats2bfloat162_rn(s8[2 * i] * sc, s8[2 * i + 1] * sc);
            pu[i] = *(uint32_t*)&h;
        }
        *(uint4*)(g_keys + key_off(row, ch)) = u;
    }
}

// -------------------- kernel 2: positive dots, full fp32 from raw inputs -----
__global__ void pos_dots(const float* __restrict__ q,
                         const float* __restrict__ docs) {
    int i = blockIdx.x;
    int w = threadIdx.x >> 5, l = threadIdx.x & 31;
    const float* qa = q + (size_t)i * DIM;
    const float* db = docs + (size_t)(i * P_POS + w) * DIM;
    float sq = 0.f, sd = 0.f, dt = 0.f;
    #pragma unroll
    for (int j = 0; j < DIM / 32; ++j) {
        float a = qa[j * 32 + l], b = db[j * 32 + l];
        sq = fmaf(a, a, sq); sd = fmaf(b, b, sd); dt = fmaf(a, b, dt);
    }
    #pragma unroll
    for (int o = 16; o > 0; o >>= 1) {
        sq += __shfl_xor_sync(0xffffffffu, sq, o);
        sd += __shfl_xor_sync(0xffffffffu, sd, o);
        dt += __shfl_xor_sync(0xffffffffu, dt, o);
    }
    if (l == 0)
        g_sa[i * P_POS + w] = dt / fmaxf(sqrtf(sq) * sqrtf(sd), 1e-12f);
}

// -------------------- kernel 3: bulk-copy pipelined bf16 GEMM + exp/rowsum ---
#define ST_A(s) (128 + (s) * 32768)
#define ST_B(s) (128 + (s) * 32768 + 16384)
#define SM_DYN  (128 + STAGES * 32768)

__global__ __launch_bounds__(256, 2) void gemm_exp_rowsum() {
    int bn = blockIdx.x, bm = blockIdx.y;
    if (bn < NQT && bn > bm) return;           // upper-triangle q-q tile: mirrored
    bool do_mirror = (bn < NQT) && (bn < bm);
    bool dtile     = (bn == bm) && (bn < NQT); // contains global diagonal

    extern __shared__ char smem[];
    __shared__ float rsum[4][128];
    __shared__ float csum[2][128];
    uint32_t sb = smem_u32(smem);
    uint32_t mb_full  = sb;
    uint32_t mb_empty = sb + 24;

    int t = threadIdx.x, warp = t >> 5, lane = t & 31;
    int wm = warp >> 2, wn = warp & 3;          // warp tile 64(M) x 32(N)
    int gr = lane >> 2, gc = lane & 3;

    if (t == 0) {
        #pragma unroll
        for (int s = 0; s < STAGES; ++s) {
            mbar_init(mb_full + s * 8, 1);
            mbar_init(mb_empty + s * 8, 8);
        }
    }
    __syncthreads();

    const unsigned char* keys = g_keys;
    size_t aoff = (size_t)bm * 16384;
    size_t boff = (size_t)bn * 16384;

    if (t == 0) {
        #pragma unroll
        for (int k = 0; k < STAGES; ++k) {
            uint32_t f = mb_full + k * 8;
            mbar_expect_tx(f, 32768);
            bulk_g2s(sb + ST_A(k), keys + (size_t)k * PLANE + aoff, 16384, f);
            bulk_g2s(sb + ST_B(k), keys + (size_t)k * PLANE + boff, 16384, f);
        }
    }

    float c[4][4][4];
    #pragma unroll
    for (int mt = 0; mt < 4; ++mt)
        #pragma unroll
        for (int nt = 0; nt < 4; ++nt)
            #pragma unroll
            for (int r = 0; r < 4; ++r) c[mt][nt][r] = 0.f;

    int a_mr = (lane & 15);
    int a_cb = (lane >> 4) * 16;
    int b_nr = ((lane >> 3) & 1) * 8 + (lane & 7);
    int b_cb = (lane >> 4) * 16;

    for (int kt = 0; kt < KTILES; ++kt) {
        int s = kt % STAGES;
        uint32_t ph = (uint32_t)((kt / STAGES) & 1);
        mbar_wait(mb_full + s * 8, ph);

        uint32_t As = sb + ST_A(s), Bs = sb + ST_B(s);
        #pragma unroll
        for (int ks = 0; ks < 4; ++ks) {
            uint32_t a[4][4], b[4][2];
            #pragma unroll
            for (int mt = 0; mt < 4; ++mt) {
                int mr = wm * 64 + mt * 16 + a_mr;
                uint32_t cb = (uint32_t)((ks * 32 + a_cb) ^ ((mr & 7) << 4));
                ldsm_x4(a[mt], As + mr * 128 + cb);
            }
            #pragma unroll
            for (int nt2 = 0; nt2 < 2; ++nt2) {
                int nr = wn * 32 + nt2 * 16 + b_nr;
                uint32_t cb = (uint32_t)((ks * 32 + b_cb) ^ ((nr & 7) << 4));
                uint32_t r4[4];
                ldsm_x4(r4, Bs + nr * 128 + cb);
                b[nt2 * 2 + 0][0] = r4[0]; b[nt2 * 2 + 0][1] = r4[2];
                b[nt2 * 2 + 1][0] = r4[1]; b[nt2 * 2 + 1][1] = r4[3];
            }
            #pragma unroll
            for (int mt = 0; mt < 4; ++mt)
                #pragma unroll
                for (int nt = 0; nt < 4; ++nt)
                    mma16816(c[mt][nt], a[mt], b[nt]);
        }

        __syncwarp();
        if (lane == 0) mbar_arrive(mb_empty + s * 8);
        if (t == 0 && kt + STAGES < KTILES) {
            mbar_wait(mb_empty + s * 8, ph);
            int ktn = kt + STAGES;
            uint32_t f = mb_full + s * 8;
            mbar_expect_tx(f, 32768);
            bulk_g2s(sb + ST_A(s), keys + (size_t)ktn * PLANE + aoff, 16384, f);
            bulk_g2s(sb + ST_B(s), keys + (size_t)ktn * PLANE + boff, 16384, f);
        }
    }

    // ---- epilogue: ex2 directly (scale folded into keys); exact diag excl ----
    float cs0[4] = {0.f, 0.f, 0.f, 0.f};
    float cs1[4] = {0.f, 0.f, 0.f, 0.f};
    #pragma unroll
    for (int mt = 0; mt < 4; ++mt) {
        float s0 = 0.f, s1 = 0.f;
        int r0 = wm * 64 + mt * 16 + gr;
        #pragma unroll
        for (int nt = 0; nt < 4; ++nt) {
            int n0 = wn * 32 + nt * 8 + 2 * gc;
            float e0 = ex2f(c[mt][nt][0]);
            float e1 = ex2f(c[mt][nt][1]);
            float e2 = ex2f(c[mt][nt][2]);
            float e3 = ex2f(c[mt][nt][3]);
            if (dtile) {                        // exact diagonal exclusion
                if (r0 == n0)         e0 = 0.f;
                if (r0 == n0 + 1)     e1 = 0.f;
                if (r0 + 8 == n0)     e2 = 0.f;
                if (r0 + 8 == n0 + 1) e3 = 0.f;
            }
            s0 += e0 + e1;  s1 += e2 + e3;
            cs0[nt] += e0 + e2;  cs1[nt] += e1 + e3;
        }
        s0 += __shfl_xor_sync(0xffffffffu, s0, 1);
        s0 += __shfl_xor_sync(0xffffffffu, s0, 2);
        s1 += __shfl_xor_sync(0xffffffffu, s1, 1);
        s1 += __shfl_xor_sync(0xffffffffu, s1, 2);
        if (gc == 0) {
            rsum[wn][wm * 64 + mt * 16 + gr]     = s0;
            rsum[wn][wm * 64 + mt * 16 + 8 + gr] = s1;
        }
    }
    if (do_mirror) {
        #pragma unroll
        for (int nt = 0; nt < 4; ++nt) {
            #pragma unroll
            for (int o = 4; o <= 16; o <<= 1) {
                cs0[nt] += __shfl_xor_sync(0xffffffffu, cs0[nt], o);
                cs1[nt] += __shfl_xor_sync(0xffffffffu, cs1[nt], o);
            }
        }
        if (gr == 0) {
            #pragma unroll
            for (int nt = 0; nt < 4; ++nt) {
                int n = wn * 32 + nt * 8 + 2 * gc;
                if (wm == 0) { csum[0][n] = cs0[nt]; csum[0][n + 1] = cs1[nt]; }
                else         { csum[1][n] = cs0[nt]; csum[1][n + 1] = cs1[nt]; }
            }
        }
    }
    __syncthreads();
    if (t < 128) {
        g_part[(size_t)(bm * BM + t) * PW + bn] =
            rsum[0][t] + rsum[1][t] + rsum[2][t] + rsum[3][t];
        if (do_mirror)
            g_part[(size_t)(bn * BN + t) * PW + 160 + bm] = csum[0][t] + csum[1][t];
    }
}

// -------------------- kernel 4: reduce partials + per-row loss ---------------
// warp per row: S = sum of 192 partials (diag already excluded), then lane 0
// computes the row's 4-term loss directly (parallel logf across 4096 warps).
__global__ void reduce_S_loss() {
    int row = blockIdx.x * 8 + (threadIdx.x >> 5);
    int l   = threadIdx.x & 31;
    float s = 0.f;
    #pragma unroll
    for (int j = 0; j < PW / 32; ++j) s += g_part[(size_t)row * PW + j * 32 + l];
    for (int o = 16; o > 0; o >>= 1) s += __shfl_xor_sync(0xffffffffu, s, o);
    if (l == 0) {
        float e[4], su = 0.f, sa[4], acc = 0.f;
        #pragma unroll
        for (int n = 0; n < 4; ++n) {
            sa[n] = g_sa[row * P_POS + n];
            e[n]  = ex2f(sa[n] * LOG2E_OVER_T);
            su   += e[n];
        }
        float base = s - su;
        #pragma unroll
        for (int n = 0; n < 4; ++n)
            acc += logf(base + e[n]) - sa[n] * INV_T;
        g_rowloss[row] = acc;
    }
}

// -------------------- kernel 5: final sum ------------------------------------
__global__ void finalize_loss(float* __restrict__ out, int out_size) {
    int t = threadIdx.x;
    float acc = 0.f;
    #pragma unroll
    for (int j = 0; j < B_Q / 512; ++j) acc += g_rowloss[j * 512 + t];
    __shared__ float red[512];
    red[t] = acc; __syncthreads();
    for (int s = 256; s > 0; s >>= 1) { if (t < s) red[t] += red[t + s]; __syncthreads(); }
    if (t == 0) {
        float loss = red[0] / (float)(B_Q * P_POS);
        for (int j = 0; j < out_size; ++j) out[j] = loss;
    }
}

// -------------------- launch --------------------------------------------------
extern "C" void kernel_launch(void* const* d_in, const int* in_sizes, int n_in,
                              void* d_out, int out_size) {
    (void)in_sizes; (void)n_in;
    const float* q    = (const float*)d_in[0];
    const float* docs = (const float*)d_in[1];
    float* out        = (float*)d_out;

    cudaFuncSetAttribute(gemm_exp_rowsum, cudaFuncAttributeMaxDynamicSharedMemorySize, SM_DYN);

    prep_normalize<<<N_KEY / 8, 256>>>(q, docs);
    pos_dots<<<B_Q, 128>>>(q, docs);
    gemm_exp_rowsum<<<dim3(NT_N, NT_M), 256, SM_DYN>>>();
    reduce_S_loss<<<B_Q / 8, 256>>>();
    finalize_loss<<<1, 512>>>(out, out_size);
}

// round 13
// speedup vs baseline: 1.1099x; 1.0182x over previous
#include <cuda_runtime.h>
#include <cuda_bf16.h>
#include <stdint.h>

// -------------------- problem constants --------------------
#define B_Q   4096
#define P_POS 4
#define DIM   768
#define N_KEY 20480               // B_Q + B_Q*P_POS

#define BM    128
#define BN    128
#define KTILES 12                 // 64 bf16 (=128B) per k-tile
#define STAGES 3
#define NT_M  (B_Q / BM)          // 32
#define NT_N  (N_KEY / BN)        // 160
#define NQT   32                  // column tiles that are query keys
#define PW    192                 // 160 direct + 32 mirror slots

// TEMPERATURE = 0.07
#define INV_T         14.285714285714286f
#define LOG2E_OVER_T  20.609929155556620f
// keys pre-scaled by sqrt(log2e/T): dot of stored keys = cos_sim * log2e/T,
// so exp(cos/T) = ex2(dot) with no epilogue multiply.
#define KEY_PRESCALE  4.539816203f

// Global key layout: k-tile-major, pre-swizzled SW128:
//   off(kt,r,c16) = kt*PLANE + (r>>3)*1024 + ((r&7)*128 + c16*16) ^ ((r&7)<<4)
#define PLANE ((size_t)N_KEY * 128)

// -------------------- scratch (__device__ globals; zero-init, no allocs) -----
__device__ __align__(256) unsigned char g_keys[(size_t)KTILES * PLANE];  // bf16
__device__ float g_part[(size_t)B_Q * PW];   // unwritten slots stay 0 forever
__device__ float g_rowloss[B_Q];
__device__ float g_sa[B_Q * P_POS];

// -------------------- PTX helpers --------------------
__device__ __forceinline__ uint32_t smem_u32(const void* p) {
    uint32_t a;
    asm("{ .reg .u64 t; cvta.to.shared.u64 t, %1; cvt.u32.u64 %0, t; }" : "=r"(a) : "l"(p));
    return a;
}
__device__ __forceinline__ float ex2f(float y) {
    float r; asm("ex2.approx.ftz.f32 %0, %1;" : "=f"(r) : "f"(y)); return r;
}
__device__ __forceinline__ void mbar_init(uint32_t a, uint32_t cnt) {
    asm volatile("mbarrier.init.shared.b64 [%0], %1;" :: "r"(a), "r"(cnt) : "memory");
}
__device__ __forceinline__ void mbar_expect_tx(uint32_t a, uint32_t bytes) {
    asm volatile("mbarrier.arrive.expect_tx.shared.b64 _, [%0], %1;" :: "r"(a), "r"(bytes) : "memory");
}
__device__ __forceinline__ void mbar_arrive(uint32_t a) {
    asm volatile("mbarrier.arrive.shared.b64 _, [%0];" :: "r"(a) : "memory");
}
__device__ __forceinline__ void mbar_wait(uint32_t a, uint32_t ph) {
    asm volatile(
        "{\n\t.reg .pred P;\n\t"
        "LAB_%=:\n\t"
        "mbarrier.try_wait.parity.acquire.cta.shared::cta.b64 P, [%0], %1, 0x989680;\n\t"
        "@!P bra LAB_%=;\n\t}"
        :: "r"(a), "r"(ph) : "memory");
}
__device__ __forceinline__ void bulk_g2s(uint32_t dst, const void* src, uint32_t bytes,
                                         uint32_t mbar) {
    asm volatile(
        "cp.async.bulk.shared::cta.global.mbarrier::complete_tx::bytes [%0], [%1], %2, [%3];"
        :: "r"(dst), "l"(src), "r"(bytes), "r"(mbar) : "memory");
}
__device__ __forceinline__ void ldsm_x4(uint32_t* r, uint32_t addr) {
    asm volatile("ldmatrix.sync.aligned.m8n8.x4.shared.b16 {%0,%1,%2,%3}, [%4];"
                 : "=r"(r[0]), "=r"(r[1]), "=r"(r[2]), "=r"(r[3]) : "r"(addr));
}
__device__ __forceinline__ void mma16816(float* c, const uint32_t* a, const uint32_t* b) {
    asm volatile(
        "mma.sync.aligned.m16n8k16.row.col.f32.bf16.bf16.f32 "
        "{%0,%1,%2,%3}, {%4,%5,%6,%7}, {%8,%9}, {%0,%1,%2,%3};"
        : "+f"(c[0]), "+f"(c[1]), "+f"(c[2]), "+f"(c[3])
        : "r"(a[0]), "r"(a[1]), "r"(a[2]), "r"(a[3]), "r"(b[0]), "r"(b[1]));
}

// chunk ch in [0,96): 16B chunk of a row (kt = ch>>3 in [0,12), c16 = ch&7)
__device__ __forceinline__ size_t key_off(int r, int ch) {
    int kt = ch >> 3, c16 = ch & 7, rr = r & 7;
    return (size_t)kt * PLANE + (size_t)(r >> 3) * 1024
         + (uint32_t)((rr * 128 + c16 * 16) ^ (rr << 4));
}

// -------------------- kernel 1: fused normalize + keys + positive dots -------
// Block i (5 warps): warp 4 = query row i, warps 0-3 = doc rows i*4+w.
// Each warp stages its RAW row into its own SMEM region (read inputs once),
// computes |row|^2 in registers, writes prescaled bf16 keys from SMEM, and
// doc warps compute fp32 positive dots against the q SMEM row.
__global__ __launch_bounds__(160) void prep_fused(const float* __restrict__ q,
                                                  const float* __restrict__ docs) {
    __shared__ float rows[5][DIM];             // 15 KB
    __shared__ float rss[5];

    int i = blockIdx.x;
    int w = threadIdx.x >> 5, l = threadIdx.x & 31;
    bool isq = (w == 4);
    int row = isq ? i : (B_Q + i * P_POS + w);
    const float* src = isq ? (q + (size_t)i * DIM)
                           : (docs + (size_t)(i * P_POS + w) * DIM);

    float v[24];
    float ss = 0.f;
    #pragma unroll
    for (int j = 0; j < 24; ++j) {
        v[j] = src[j * 32 + l];
        rows[w][j * 32 + l] = v[j];
        ss = fmaf(v[j], v[j], ss);
    }
    #pragma unroll
    for (int o = 16; o > 0; o >>= 1) ss += __shfl_xor_sync(0xffffffffu, ss, o);
    if (l == 0) rss[w] = ss;
    __syncthreads();

    // write prescaled bf16 keys: lane handles 3 chunks of 8 contiguous elems,
    // read from own warp's SMEM row (no cross-lane register indexing).
    float sc = KEY_PRESCALE / fmaxf(sqrtf(ss), 1e-12f);
    #pragma unroll
    for (int c3 = 0; c3 < 3; ++c3) {
        int ch = c3 * 32 + l;
        const float* s8 = &rows[w][ch * 8];
        uint4 u;
        uint32_t* pu = (uint32_t*)&u;
        #pragma unroll
        for (int e = 0; e < 4; ++e) {
            __nv_bfloat162 h = __floats2bfloat162_rn(s8[2 * e] * sc, s8[2 * e + 1] * sc);
            pu[e] = *(uint32_t*)&h;
        }
        *(uint4*)(g_keys + key_off(row, ch)) = u;
    }

    // positive dots in fp32 (doc warps vs q row in SMEM)
    if (!isq) {
        float dt = 0.f;
        #pragma unroll
        for (int j = 0; j < 24; ++j) dt = fmaf(rows[4][j * 32 + l], v[j], dt);
        #pragma unroll
        for (int o = 16; o > 0; o >>= 1) dt += __shfl_xor_sync(0xffffffffu, dt, o);
        if (l == 0)
            g_sa[i * P_POS + w] = dt / fmaxf(sqrtf(rss[4]) * sqrtf(ss), 1e-12f);
    }
}

// -------------------- kernel 2: bulk-copy pipelined bf16 GEMM + exp/rowsum ---
#define ST_A(s) (128 + (s) * 32768)
#define ST_B(s) (128 + (s) * 32768 + 16384)
#define SM_DYN  (128 + STAGES * 32768)

__global__ __launch_bounds__(256, 2) void gemm_exp_rowsum() {
    int bn = blockIdx.x, bm = blockIdx.y;
    if (bn < NQT && bn > bm) return;           // upper-triangle q-q tile: mirrored
    bool do_mirror = (bn < NQT) && (bn < bm);
    bool dtile     = (bn == bm) && (bn < NQT); // contains global diagonal

    extern __shared__ char smem[];
    __shared__ float rsum[4][128];
    __shared__ float csum[2][128];
    uint32_t sb = smem_u32(smem);
    uint32_t mb_full  = sb;
    uint32_t mb_empty = sb + 24;

    int t = threadIdx.x, warp = t >> 5, lane = t & 31;
    int wm = warp >> 2, wn = warp & 3;          // warp tile 64(M) x 32(N)
    int gr = lane >> 2, gc = lane & 3;

    if (t == 0) {
        #pragma unroll
        for (int s = 0; s < STAGES; ++s) {
            mbar_init(mb_full + s * 8, 1);
            mbar_init(mb_empty + s * 8, 8);
        }
    }
    __syncthreads();

    const unsigned char* keys = g_keys;
    size_t aoff = (size_t)bm * 16384;
    size_t boff = (size_t)bn * 16384;

    if (t == 0) {
        #pragma unroll
        for (int k = 0; k < STAGES; ++k) {
            uint32_t f = mb_full + k * 8;
            mbar_expect_tx(f, 32768);
            bulk_g2s(sb + ST_A(k), keys + (size_t)k * PLANE + aoff, 16384, f);
            bulk_g2s(sb + ST_B(k), keys + (size_t)k * PLANE + boff, 16384, f);
        }
    }

    float c[4][4][4];
    #pragma unroll
    for (int mt = 0; mt < 4; ++mt)
        #pragma unroll
        for (int nt = 0; nt < 4; ++nt)
            #pragma unroll
            for (int r = 0; r < 4; ++r) c[mt][nt][r] = 0.f;

    int a_mr = (lane & 15);
    int a_cb = (lane >> 4) * 16;
    int b_nr = ((lane >> 3) & 1) * 8 + (lane & 7);
    int b_cb = (lane >> 4) * 16;

    for (int kt = 0; kt < KTILES; ++kt) {
        int s = kt % STAGES;
        uint32_t ph = (uint32_t)((kt / STAGES) & 1);
        mbar_wait(mb_full + s * 8, ph);

        uint32_t As = sb + ST_A(s), Bs = sb + ST_B(s);
        #pragma unroll
        for (int ks = 0; ks < 4; ++ks) {
            uint32_t a[4][4], b[4][2];
            #pragma unroll
            for (int mt = 0; mt < 4; ++mt) {
                int mr = wm * 64 + mt * 16 + a_mr;
                uint32_t cb = (uint32_t)((ks * 32 + a_cb) ^ ((mr & 7) << 4));
                ldsm_x4(a[mt], As + mr * 128 + cb);
            }
            #pragma unroll
            for (int nt2 = 0; nt2 < 2; ++nt2) {
                int nr = wn * 32 + nt2 * 16 + b_nr;
                uint32_t cb = (uint32_t)((ks * 32 + b_cb) ^ ((nr & 7) << 4));
                uint32_t r4[4];
                ldsm_x4(r4, Bs + nr * 128 + cb);
                b[nt2 * 2 + 0][0] = r4[0]; b[nt2 * 2 + 0][1] = r4[2];
                b[nt2 * 2 + 1][0] = r4[1]; b[nt2 * 2 + 1][1] = r4[3];
            }
            #pragma unroll
            for (int mt = 0; mt < 4; ++mt)
                #pragma unroll
                for (int nt = 0; nt < 4; ++nt)
                    mma16816(c[mt][nt], a[mt], b[nt]);
        }

        __syncwarp();
        if (lane == 0) mbar_arrive(mb_empty + s * 8);
        if (t == 0 && kt + STAGES < KTILES) {
            mbar_wait(mb_empty + s * 8, ph);
            int ktn = kt + STAGES;
            uint32_t f = mb_full + s * 8;
            mbar_expect_tx(f, 32768);
            bulk_g2s(sb + ST_A(s), keys + (size_t)ktn * PLANE + aoff, 16384, f);
            bulk_g2s(sb + ST_B(s), keys + (size_t)ktn * PLANE + boff, 16384, f);
        }
    }

    // ---- epilogue: ex2 directly (scale folded into keys); exact diag excl ----
    float cs0[4] = {0.f, 0.f, 0.f, 0.f};
    float cs1[4] = {0.f, 0.f, 0.f, 0.f};
    #pragma unroll
    for (int mt = 0; mt < 4; ++mt) {
        float s0 = 0.f, s1 = 0.f;
        int r0 = wm * 64 + mt * 16 + gr;
        #pragma unroll
        for (int nt = 0; nt < 4; ++nt) {
            int n0 = wn * 32 + nt * 8 + 2 * gc;
            float e0 = ex2f(c[mt][nt][0]);
            float e1 = ex2f(c[mt][nt][1]);
            float e2 = ex2f(c[mt][nt][2]);
            float e3 = ex2f(c[mt][nt][3]);
            if (dtile) {                        // exact diagonal exclusion
                if (r0 == n0)         e0 = 0.f;
                if (r0 == n0 + 1)     e1 = 0.f;
                if (r0 + 8 == n0)     e2 = 0.f;
                if (r0 + 8 == n0 + 1) e3 = 0.f;
            }
            s0 += e0 + e1;  s1 += e2 + e3;
            cs0[nt] += e0 + e2;  cs1[nt] += e1 + e3;
        }
        s0 += __shfl_xor_sync(0xffffffffu, s0, 1);
        s0 += __shfl_xor_sync(0xffffffffu, s0, 2);
        s1 += __shfl_xor_sync(0xffffffffu, s1, 1);
        s1 += __shfl_xor_sync(0xffffffffu, s1, 2);
        if (gc == 0) {
            rsum[wn][wm * 64 + mt * 16 + gr]     = s0;
            rsum[wn][wm * 64 + mt * 16 + 8 + gr] = s1;
        }
    }
    if (do_mirror) {
        #pragma unroll
        for (int nt = 0; nt < 4; ++nt) {
            #pragma unroll
            for (int o = 4; o <= 16; o <<= 1) {
                cs0[nt] += __shfl_xor_sync(0xffffffffu, cs0[nt], o);
                cs1[nt] += __shfl_xor_sync(0xffffffffu, cs1[nt], o);
            }
        }
        if (gr == 0) {
            #pragma unroll
            for (int nt = 0; nt < 4; ++nt) {
                int n = wn * 32 + nt * 8 + 2 * gc;
                if (wm == 0) { csum[0][n] = cs0[nt]; csum[0][n + 1] = cs1[nt]; }
                else         { csum[1][n] = cs0[nt]; csum[1][n + 1] = cs1[nt]; }
            }
        }
    }
    __syncthreads();
    if (t < 128) {
        g_part[(size_t)(bm * BM + t) * PW + bn] =
            rsum[0][t] + rsum[1][t] + rsum[2][t] + rsum[3][t];
        if (do_mirror)
            g_part[(size_t)(bn * BN + t) * PW + 160 + bm] = csum[0][t] + csum[1][t];
    }
}

// -------------------- kernel 3: reduce partials + per-row loss ---------------
__global__ void reduce_S_loss() {
    int row = blockIdx.x * 8 + (threadIdx.x >> 5);
    int l   = threadIdx.x & 31;
    float s = 0.f;
    #pragma unroll
    for (int j = 0; j < PW / 32; ++j) s += g_part[(size_t)row * PW + j * 32 + l];
    for (int o = 16; o > 0; o >>= 1) s += __shfl_xor_sync(0xffffffffu, s, o);
    if (l == 0) {
        float e[4], su = 0.f, sa[4], acc = 0.f;
        #pragma unroll
        for (int n = 0; n < 4; ++n) {
            sa[n] = g_sa[row * P_POS + n];
            e[n]  = ex2f(sa[n] * LOG2E_OVER_T);
            su   += e[n];
        }
        float base = s - su;
        #pragma unroll
        for (int n = 0; n < 4; ++n)
            acc += logf(base + e[n]) - sa[n] * INV_T;
        g_rowloss[row] = acc;
    }
}

// -------------------- kernel 4: final sum ------------------------------------
__global__ void finalize_loss(float* __restrict__ out, int out_size) {
    int t = threadIdx.x;
    float acc = 0.f;
    #pragma unroll
    for (int j = 0; j < B_Q / 512; ++j) acc += g_rowloss[j * 512 + t];
    __shared__ float red[512];
    red[t] = acc; __syncthreads();
    for (int s = 256; s > 0; s >>= 1) { if (t < s) red[t] += red[t + s]; __syncthreads(); }
    if (t == 0) {
        float loss = red[0] / (float)(B_Q * P_POS);
        for (int j = 0; j < out_size; ++j) out[j] = loss;
    }
}

// -------------------- launch --------------------------------------------------
extern "C" void kernel_launch(void* const* d_in, const int* in_sizes, int n_in,
                              void* d_out, int out_size) {
    (void)in_sizes; (void)n_in;
    const float* q    = (const float*)d_in[0];
    const float* docs = (const float*)d_in[1];
    float* out        = (float*)d_out;

    cudaFuncSetAttribute(gemm_exp_rowsum, cudaFuncAttributeMaxDynamicSharedMemorySize, SM_DYN);

    prep_fused<<<B_Q, 160>>>(q, docs);
    gemm_exp_rowsum<<<dim3(NT_N, NT_M), 256, SM_DYN>>>();
    reduce_S_loss<<<B_Q / 8, 256>>>();
    finalize_loss<<<1, 512>>>(out, out_size);
}